// round 4
// baseline (speedup 1.0000x reference)
#include <cuda_runtime.h>
#include <cuda_bf16.h>
#include <cstdint>

// Problem constants
#define N_STREAMS 8
#define D_MODEL   2048
#define NS        16
#define N_SKEW    120
#define KPAD      128
#define TOKENS    8192
#define TPC       8
#define THREADS   256
#define NTILES    (TOKENS / TPC)      // 1024
#define DP_TOTAL  (D_MODEL / 2)       // 1024

// Chunked pipeline
#define NC   16                       // chunks
#define DC   (D_MODEL / NC)           // 128 floats per chunk per token
#define DC4  (DC / 4)                 // 32 float4
#define DPC  (DC / 2)                 // 64 dpairs per chunk

// W transposed + f32x2-packed: g_Wt2[dp*KPAD + k] = (W[k][2dp], W[k][2dp+1]); 0 for k>=120
__device__ float2 g_Wt2[DP_TOTAL * KPAD];   // 1 MB

__global__ void prep_wt_kernel(const float* __restrict__ W) {
    int id = blockIdx.x * blockDim.x + threadIdx.x;
    int dp = id & (DP_TOTAL - 1);
    int k  = id >> 10;
    float2 v = make_float2(0.f, 0.f);
    if (k < N_SKEW) {
        v.x = W[k * D_MODEL + 2 * dp];
        v.y = W[k * D_MODEL + 2 * dp + 1];
    }
    g_Wt2[dp * KPAD + k] = v;
}

__device__ __forceinline__ void fma2(unsigned long long& acc,
                                     unsigned long long a,
                                     unsigned long long b) {
    asm("fma.rn.f32x2 %0, %1, %2, %0;" : "+l"(acc) : "l"(a), "l"(b));
}

extern "C" __global__ void __launch_bounds__(THREADS, 3)
gomhc_fused_kernel(const float* __restrict__ streams,
                   const float* __restrict__ bias,
                   float* __restrict__ out) {
    __shared__ float xs[2][TPC * DC];   // 2 x 4 KB mean tiles
    __shared__ float zs[TPC * KPAD];    // 4 KB

    const int tid  = threadIdx.x;
    const int tile = blockIdx.x;

    for (int i = tid; i < TPC * KPAD; i += THREADS) zs[i] = 0.f;

    // ---- load mapping: one (token, float4-slot) per thread ----
    const int lt = tid >> 5;            // token 0..7 (warp per token)
    const int lf = tid & 31;            // float4 slot within chunk
    const float4* sbase = reinterpret_cast<const float4*>(streams)
                        + (size_t)tile * TPC * (N_STREAMS * D_MODEL / 4)
                        + lt * (N_STREAMS * D_MODEL / 4) + lf;

    // ---- GEMV mapping: k = {2kg, 2kg+1}; ds = quarter of chunk (16 dp) ----
    const int kg = tid & 63;
    const int ds = tid >> 6;            // 0..3

    unsigned long long acc0[TPC], acc1[TPC];
    #pragma unroll
    for (int t = 0; t < TPC; t++) { acc0[t] = 0ull; acc1[t] = 0ull; }

    // prologue: chunk-0 loads
    float4 R[N_STREAMS];
    #pragma unroll
    for (int n = 0; n < N_STREAMS; n++)
        R[n] = sbase[n * (D_MODEL / 4)];

    #pragma unroll 1
    for (int c = 0; c < NC; c++) {
        // reduce streams -> mean, store to xs[c&1]
        #pragma unroll
        for (int s = N_STREAMS / 2; s > 0; s >>= 1)
            #pragma unroll
            for (int n = 0; n < s; n++) {
                R[n].x += R[n + s].x; R[n].y += R[n + s].y;
                R[n].z += R[n + s].z; R[n].w += R[n + s].w;
            }
        R[0].x *= 0.125f; R[0].y *= 0.125f; R[0].z *= 0.125f; R[0].w *= 0.125f;
        reinterpret_cast<float4*>(xs[c & 1])[lt * DC4 + lf] = R[0];

        __syncthreads();

        // issue next chunk's loads (fly behind GEMV)
        if (c + 1 < NC) {
            const float4* nb = sbase + (c + 1) * DC4;
            #pragma unroll
            for (int n = 0; n < N_STREAMS; n++)
                R[n] = nb[n * (D_MODEL / 4)];
        }

        // GEMV slice
        {
            const float* xb = xs[c & 1] + 2 * (ds * 16);
            const ulonglong2* __restrict__ wp =
                reinterpret_cast<const ulonglong2*>(g_Wt2)
                + (size_t)(c * DPC + ds * 16) * (KPAD / 2) + kg;
            #pragma unroll 4
            for (int j = 0; j < 16; j++) {
                ulonglong2 w = wp[j * (KPAD / 2)];
                const float* xr = xb + 2 * j;
                #pragma unroll
                for (int t = 0; t < TPC; t++) {
                    unsigned long long x2 =
                        *reinterpret_cast<const unsigned long long*>(xr + t * DC);
                    fma2(acc0[t], w.x, x2);
                    fma2(acc1[t], w.y, x2);
                }
            }
        }
    }

    // ---- reduce 4 d-quarter partials via shared atomics ----
    #pragma unroll
    for (int t = 0; t < TPC; t++) {
        float2 a = *reinterpret_cast<float2*>(&acc0[t]);
        float2 b = *reinterpret_cast<float2*>(&acc1[t]);
        atomicAdd(&zs[t * KPAD + 2 * kg    ], a.x + a.y);
        atomicAdd(&zs[t * KPAD + 2 * kg + 1], b.x + b.y);
    }
    __syncthreads();

    for (int i = tid; i < TPC * N_SKEW; i += THREADS) {
        int t = i / N_SKEW, k = i - t * N_SKEW;
        zs[t * KPAD + k] += bias[k];
    }
    __syncthreads();

    // ---- Phase C: Cayley solve + block Frobenius, one warp per token ----
    {
        const int warp = tid >> 5;          // token 0..7
        const int lane = tid & 31;
        const int r    = lane & 15;
        const float* zt = zs + warp * KPAD;

        float m[32];
        #pragma unroll
        for (int cc = 0; cc < NS; cc++) {
            float a = 0.f;
            if (cc > r)      a =  zt[(r * (31 - r)) / 2 + (cc - r - 1)];
            else if (cc < r) a = -zt[(cc * (31 - cc)) / 2 + (r - cc - 1)];
            float diag = (cc == r) ? 1.f : 0.f;
            m[cc]      = diag + a;
            m[16 + cc] = diag - a;
        }

        // Gauss-Jordan, uniform-coefficient form (no pivot-row array)
        const unsigned mask = 0xffffffffu;
        #pragma unroll
        for (int i = 0; i < NS; i++) {
            float pivi = __shfl_sync(mask, m[i], i);
            float rp = 1.0f / pivi;
            float cf = (r == i) ? (1.0f - rp) : m[i] * rp;
            #pragma unroll
            for (int k = 0; k < 32; k++) {
                float pk = __shfl_sync(mask, m[k], i);
                m[k] = fmaf(-cf, pk, m[k]);
            }
        }

        float hq[8];
        #pragma unroll
        for (int q = 0; q < 8; q++) {
            float q0 = m[16 + 2 * q], q1 = m[16 + 2 * q + 1];
            hq[q] = q0 * q0 + q1 * q1;
        }
        #pragma unroll
        for (int q = 0; q < 8; q++)
            hq[q] += __shfl_xor_sync(mask, hq[q], 1);

        if (lane < 16 && !(r & 1)) {
            const int tok = tile * TPC + warp;
            float* o = out + (size_t)tok * 64 + (r >> 1) * 8;
            #pragma unroll
            for (int q = 0; q < 8; q++) o[q] = 0.5f * hq[q];
        }
    }
}

extern "C" void kernel_launch(void* const* d_in, const int* in_sizes, int n_in,
                              void* d_out, int out_size) {
    const float* streams = (const float*)d_in[0];
    const float* W       = (const float*)d_in[1];
    const float* b       = (const float*)d_in[2];
    float* out = (float*)d_out;

    prep_wt_kernel<<<(DP_TOTAL * KPAD) / 256, 256>>>(W);
    gomhc_fused_kernel<<<NTILES, THREADS>>>(streams, b, out);
}

// round 5
// speedup vs baseline: 1.0475x; 1.0475x over previous
#include <cuda_runtime.h>
#include <cuda_bf16.h>
#include <cstdint>

// Problem constants
#define N_STREAMS 8
#define D_MODEL   2048
#define NS        16
#define N_SKEW    120
#define KPAD      128
#define TOKENS    8192
#define TPC       16
#define THREADS   512
#define NTILES    (TOKENS / TPC)      // 512
#define DP_TOTAL  (D_MODEL / 2)       // 1024

// Scratch
__device__ float2 g_Wt2[DP_TOTAL * KPAD];        // 1 MB, W^T f32x2-packed
__device__ float  g_xagg[TOKENS * D_MODEL];      // 64 MB, mean over streams

__global__ void prep_wt_kernel(const float* __restrict__ W) {
    int id = blockIdx.x * blockDim.x + threadIdx.x;
    int dp = id & (DP_TOTAL - 1);
    int k  = id >> 10;
    float2 v = make_float2(0.f, 0.f);
    if (k < N_SKEW) {
        v.x = W[k * D_MODEL + 2 * dp];
        v.y = W[k * D_MODEL + 2 * dp + 1];
    }
    g_Wt2[dp * KPAD + k] = v;
}

// ---------------- K1: mean over streams (pure streaming) ----------------
// one (token, float4-slot) per thread; 8 strided LDG.128, tree-reduce, 1 STG.128
__global__ void __launch_bounds__(256)
mean_kernel(const float* __restrict__ streams) {
    int idx   = blockIdx.x * 256 + threadIdx.x;      // [0, TOKENS*512)
    int token = idx >> 9;
    int slot  = idx & 511;
    const float4* tb = reinterpret_cast<const float4*>(streams)
                     + (size_t)token * (N_STREAMS * D_MODEL / 4) + slot;
    float4 v[N_STREAMS];
    #pragma unroll
    for (int n = 0; n < N_STREAMS; n++) v[n] = tb[n * (D_MODEL / 4)];
    #pragma unroll
    for (int s = N_STREAMS / 2; s > 0; s >>= 1)
        #pragma unroll
        for (int n = 0; n < s; n++) {
            v[n].x += v[n+s].x; v[n].y += v[n+s].y;
            v[n].z += v[n+s].z; v[n].w += v[n+s].w;
        }
    v[0].x *= 0.125f; v[0].y *= 0.125f; v[0].z *= 0.125f; v[0].w *= 0.125f;
    reinterpret_cast<float4*>(g_xagg)[idx] = v[0];
}

__device__ __forceinline__ void fma2(unsigned long long& acc,
                                     unsigned long long a,
                                     unsigned long long b) {
    asm("fma.rn.f32x2 %0, %1, %2, %0;" : "+l"(acc) : "l"(a), "l"(b));
}

// ---------------- K2: GEMV + Cayley solve ----------------
#define SMEM_FLOATS (TPC * D_MODEL + TPC * KPAD)
#define SMEM_BYTES  (SMEM_FLOATS * 4)

extern "C" __global__ void __launch_bounds__(THREADS, 1)
gemv_solve_kernel(const float* __restrict__ bias,
                  float* __restrict__ out) {
    extern __shared__ float smem[];
    float* xs = smem;                   // [16][2048]
    float* zs = smem + TPC * D_MODEL;   // [16][128]

    const int tid  = threadIdx.x;
    const int tile = blockIdx.x;

    for (int i = tid; i < TPC * KPAD; i += THREADS) zs[i] = 0.f;

    // ---- load x tile (coalesced, 16 float4 per thread) ----
    {
        const float4* gx = reinterpret_cast<const float4*>(g_xagg)
                         + (size_t)tile * (TPC * D_MODEL / 4);
        float4* xs4 = reinterpret_cast<float4*>(xs);
        #pragma unroll
        for (int j = 0; j < TPC * D_MODEL / 4 / THREADS; j++)
            xs4[tid + j * THREADS] = gx[tid + j * THREADS];
    }
    __syncthreads();

    // ---- GEMV: kg = tid&63 -> k={2kg,2kg+1}; ds = tid>>6 -> 8-way d-split ----
    {
        const int kg = tid & 63;
        const int ds = tid >> 6;

        const ulonglong2* __restrict__ wp =
            reinterpret_cast<const ulonglong2*>(g_Wt2)
            + (size_t)(ds * (DP_TOTAL / 8)) * (KPAD / 2) + kg;

        unsigned long long acc0[TPC], acc1[TPC];
        #pragma unroll
        for (int t = 0; t < TPC; t++) { acc0[t] = 0ull; acc1[t] = 0ull; }

        const float* xb = xs + 2 * (ds * (DP_TOTAL / 8));

        // 2-deep W prefetch to hide L2 latency
        ulonglong2 wcur = wp[0];
        ulonglong2 wnxt = wp[KPAD / 2];

        #pragma unroll 2
        for (int j = 0; j < DP_TOTAL / 8; j++) {
            ulonglong2 w = wcur;
            wcur = wnxt;
            if (j + 2 < DP_TOTAL / 8) wnxt = wp[(j + 2) * (KPAD / 2)];
            const float* xr = xb + 2 * j;
            #pragma unroll
            for (int t = 0; t < TPC; t++) {
                unsigned long long x2 =
                    *reinterpret_cast<const unsigned long long*>(xr + t * D_MODEL);
                fma2(acc0[t], w.x, x2);
                fma2(acc1[t], w.y, x2);
            }
        }

        #pragma unroll
        for (int t = 0; t < TPC; t++) {
            float2 a = *reinterpret_cast<float2*>(&acc0[t]);
            float2 b = *reinterpret_cast<float2*>(&acc1[t]);
            atomicAdd(&zs[t * KPAD + 2 * kg    ], a.x + a.y);
            atomicAdd(&zs[t * KPAD + 2 * kg + 1], b.x + b.y);
        }
    }
    __syncthreads();

    for (int i = tid; i < TPC * N_SKEW; i += THREADS) {
        int t = i / N_SKEW, k = i - t * N_SKEW;
        zs[t * KPAD + k] += bias[k];
    }
    __syncthreads();

    // ---- Cayley solve + block Frobenius, one warp per token ----
    {
        const int warp = tid >> 5;
        const int lane = tid & 31;
        const int r    = lane & 15;
        const float* zt = zs + warp * KPAD;

        float m[32];
        #pragma unroll
        for (int cc = 0; cc < NS; cc++) {
            float a = 0.f;
            if (cc > r)      a =  zt[(r * (31 - r)) / 2 + (cc - r - 1)];
            else if (cc < r) a = -zt[(cc * (31 - cc)) / 2 + (r - cc - 1)];
            float diag = (cc == r) ? 1.f : 0.f;
            m[cc]      = diag + a;
            m[16 + cc] = diag - a;
        }

        const unsigned mask = 0xffffffffu;
        #pragma unroll
        for (int i = 0; i < NS; i++) {
            float pivi = __shfl_sync(mask, m[i], i);
            float rp = 1.0f / pivi;
            float cf = (r == i) ? (1.0f - rp) : m[i] * rp;
            #pragma unroll
            for (int k = 0; k < 32; k++) {
                float pk = __shfl_sync(mask, m[k], i);
                m[k] = fmaf(-cf, pk, m[k]);
            }
        }

        float hq[8];
        #pragma unroll
        for (int q = 0; q < 8; q++) {
            float q0 = m[16 + 2 * q], q1 = m[16 + 2 * q + 1];
            hq[q] = q0 * q0 + q1 * q1;
        }
        #pragma unroll
        for (int q = 0; q < 8; q++)
            hq[q] += __shfl_xor_sync(mask, hq[q], 1);

        if (lane < 16 && !(r & 1)) {
            const int tok = tile * TPC + warp;
            float* o = out + (size_t)tok * 64 + (r >> 1) * 8;
            #pragma unroll
            for (int q = 0; q < 8; q++) o[q] = 0.5f * hq[q];
        }
    }
}

extern "C" void kernel_launch(void* const* d_in, const int* in_sizes, int n_in,
                              void* d_out, int out_size) {
    const float* streams = (const float*)d_in[0];
    const float* W       = (const float*)d_in[1];
    const float* b       = (const float*)d_in[2];
    float* out = (float*)d_out;

    prep_wt_kernel<<<(DP_TOTAL * KPAD) / 256, 256>>>(W);
    mean_kernel<<<TOKENS * (D_MODEL / 4) / 256, 256>>>(streams);

    cudaFuncSetAttribute(gemv_solve_kernel,
                         cudaFuncAttributeMaxDynamicSharedMemorySize, SMEM_BYTES);
    gemv_solve_kernel<<<NTILES, THREADS, SMEM_BYTES>>>(b, out);
}

// round 6
// speedup vs baseline: 1.1884x; 1.1345x over previous
#include <cuda_runtime.h>
#include <cuda_bf16.h>
#include <cstdint>

// Problem constants
#define N_STREAMS 8
#define D_MODEL   2048
#define NS        16
#define N_SKEW    120
#define KPAD      128
#define TOKENS    8192
#define TPC       16
#define THREADS   256
#define NTILES    (TOKENS / TPC)      // 512
#define DP_TOTAL  (D_MODEL / 2)       // 1024

// Chunked pipeline: 32 chunks of 64 floats
#define NC   32
#define DC   (D_MODEL / NC)           // 64 floats
#define DC4  (DC / 4)                 // 16 float4
#define DPC  (DC / 2)                 // 32 dpairs

// W transposed + f32x2-packed: g_Wt2[dp*KPAD + k] = (W[k][2dp], W[k][2dp+1]); 0 for k>=120
__device__ float2 g_Wt2[DP_TOTAL * KPAD];   // 1 MB

__global__ void prep_wt_kernel(const float* __restrict__ W) {
    int id = blockIdx.x * blockDim.x + threadIdx.x;
    int dp = id & (DP_TOTAL - 1);
    int k  = id >> 10;
    float2 v = make_float2(0.f, 0.f);
    if (k < N_SKEW) {
        v.x = W[k * D_MODEL + 2 * dp];
        v.y = W[k * D_MODEL + 2 * dp + 1];
    }
    g_Wt2[dp * KPAD + k] = v;
}

__device__ __forceinline__ void fma2(unsigned long long& acc,
                                     unsigned long long a,
                                     unsigned long long b) {
    asm("fma.rn.f32x2 %0, %1, %2, %0;" : "+l"(acc) : "l"(a), "l"(b));
}

extern "C" __global__ void __launch_bounds__(THREADS, 2)
gomhc_fused_kernel(const float* __restrict__ streams,
                   const float* __restrict__ bias,
                   float* __restrict__ out) {
    __shared__ float xs[2][TPC * DC];   // 2 x 4 KB mean tiles
    __shared__ float zs[TPC * KPAD];    // 8 KB

    const int tid  = threadIdx.x;
    const int tile = blockIdx.x;

    for (int i = tid; i < TPC * KPAD; i += THREADS) zs[i] = 0.f;

    // ---- Phase A mapping: one (token, float4-slot) per thread per chunk ----
    const int lt = tid >> 4;            // token 0..15
    const int lf = tid & 15;            // float4 slot within chunk (DC4=16)
    const float4* sbase = reinterpret_cast<const float4*>(streams)
                        + (size_t)tile * TPC * (N_STREAMS * D_MODEL / 4)
                        + lt * (N_STREAMS * D_MODEL / 4) + lf;
    // stream stride = D_MODEL/4 = 512 float4; chunk offset = c*DC4

    // ---- GEMV mapping: kg = tid&63 -> k = {2kg,2kg+1}; ds = tid>>6 (4-way d-split) ----
    const int kg = tid & 63;
    const int ds = tid >> 6;            // 0..3, 8 dp each per chunk

    unsigned long long acc0[TPC], acc1[TPC];
    #pragma unroll
    for (int t = 0; t < TPC; t++) { acc0[t] = 0ull; acc1[t] = 0ull; }

    // prologue: chunk-0 loads
    float4 R[N_STREAMS];
    #pragma unroll
    for (int n = 0; n < N_STREAMS; n++)
        R[n] = sbase[n * (D_MODEL / 4)];

    #pragma unroll 1
    for (int c = 0; c < NC; c++) {
        // reduce streams -> mean, store to xs[c&1]
        #pragma unroll
        for (int s = N_STREAMS / 2; s > 0; s >>= 1)
            #pragma unroll
            for (int n = 0; n < s; n++) {
                R[n].x += R[n + s].x; R[n].y += R[n + s].y;
                R[n].z += R[n + s].z; R[n].w += R[n + s].w;
            }
        R[0].x *= 0.125f; R[0].y *= 0.125f; R[0].z *= 0.125f; R[0].w *= 0.125f;
        reinterpret_cast<float4*>(xs[c & 1])[lt * DC4 + lf] = R[0];

        __syncthreads();

        // issue next chunk's loads (fly behind the GEMV below)
        if (c + 1 < NC) {
            const float4* nb = sbase + (c + 1) * DC4;
            #pragma unroll
            for (int n = 0; n < N_STREAMS; n++)
                R[n] = nb[n * (D_MODEL / 4)];
        }

        // GEMV slice: 8 dpairs for this thread's d-split
        {
            const float* xb = xs[c & 1] + 2 * (ds * 8);
            const ulonglong2* __restrict__ wp =
                reinterpret_cast<const ulonglong2*>(g_Wt2)
                + (size_t)(c * DPC + ds * 8) * (KPAD / 2) + kg;
            #pragma unroll
            for (int j = 0; j < 8; j++) {
                ulonglong2 w = wp[j * (KPAD / 2)];
                const float* xr = xb + 2 * j;
                #pragma unroll
                for (int t = 0; t < TPC; t++) {
                    unsigned long long x2 =
                        *reinterpret_cast<const unsigned long long*>(xr + t * DC);
                    fma2(acc0[t], w.x, x2);
                    fma2(acc1[t], w.y, x2);
                }
            }
        }
        // One sync per chunk is safe: STS(c+2) into this buffer happens only
        // after sync#(c+1), which itself requires all warps to finish GEMV(c).
    }

    // ---- reduce the 4 d-split partials via shared atomics ----
    #pragma unroll
    for (int t = 0; t < TPC; t++) {
        float2 a = *reinterpret_cast<float2*>(&acc0[t]);
        float2 b = *reinterpret_cast<float2*>(&acc1[t]);
        atomicAdd(&zs[t * KPAD + 2 * kg    ], a.x + a.y);
        atomicAdd(&zs[t * KPAD + 2 * kg + 1], b.x + b.y);
    }
    __syncthreads();

    for (int i = tid; i < TPC * N_SKEW; i += THREADS) {
        int t = i / N_SKEW, k = i - t * N_SKEW;
        zs[t * KPAD + k] += bias[k];
    }
    __syncthreads();

    // ---- Phase C: Cayley solve + block Frobenius; 8 warps x 2 tokens ----
    {
        const int warp = tid >> 5;          // 0..7
        const int lane = tid & 31;
        const int r    = lane & 15;
        const unsigned mask = 0xffffffffu;

        #pragma unroll 1
        for (int tt = 0; tt < 2; tt++) {
            const int token = warp * 2 + tt;
            const float* zt = zs + token * KPAD;

            float m[32];
            #pragma unroll
            for (int cc = 0; cc < NS; cc++) {
                float a = 0.f;
                if (cc > r)      a =  zt[(r * (31 - r)) / 2 + (cc - r - 1)];
                else if (cc < r) a = -zt[(cc * (31 - cc)) / 2 + (r - cc - 1)];
                float diag = (cc == r) ? 1.f : 0.f;
                m[cc]      = diag + a;
                m[16 + cc] = diag - a;
            }

            #pragma unroll
            for (int i = 0; i < NS; i++) {
                float pivi = __shfl_sync(mask, m[i], i);
                float rp = 1.0f / pivi;
                float cf = (r == i) ? (1.0f - rp) : m[i] * rp;
                #pragma unroll
                for (int k = 0; k < 32; k++) {
                    float pk = __shfl_sync(mask, m[k], i);
                    m[k] = fmaf(-cf, pk, m[k]);
                }
            }

            float hq[8];
            #pragma unroll
            for (int q = 0; q < 8; q++) {
                float q0 = m[16 + 2 * q], q1 = m[16 + 2 * q + 1];
                hq[q] = q0 * q0 + q1 * q1;
            }
            #pragma unroll
            for (int q = 0; q < 8; q++)
                hq[q] += __shfl_xor_sync(mask, hq[q], 1);

            if (lane < 16 && !(r & 1)) {
                const int tok = tile * TPC + token;
                float* o = out + (size_t)tok * 64 + (r >> 1) * 8;
                #pragma unroll
                for (int q = 0; q < 8; q++) o[q] = 0.5f * hq[q];
            }
        }
    }
}

extern "C" void kernel_launch(void* const* d_in, const int* in_sizes, int n_in,
                              void* d_out, int out_size) {
    const float* streams = (const float*)d_in[0];
    const float* W       = (const float*)d_in[1];
    const float* b       = (const float*)d_in[2];
    float* out = (float*)d_out;

    prep_wt_kernel<<<(DP_TOTAL * KPAD) / 256, 256>>>(W);
    gomhc_fused_kernel<<<NTILES, THREADS>>>(streams, b, out);
}

// round 8
// speedup vs baseline: 1.5968x; 1.3437x over previous
#include <cuda_runtime.h>
#include <cuda_bf16.h>
#include <cstdint>

// ---------------- problem constants ----------------
#define N_STREAMS 8
#define D_MODEL   2048
#define NS        16
#define N_SKEW    120
#define KPAD      128
#define TOKENS    8192

// GEMM tiling
#define TILE_M    64
#define M_TILES   (TOKENS / TILE_M)    // 128
#define KSEGS     2
#define KSEG_D    (D_MODEL / KSEGS)    // 1024
#define KC        64                   // d per smem chunk
#define N_KC      (KSEG_D / KC)        // 16
#define PITCH     72                   // bf16 row pitch in smem (144 B)

// ---------------- device scratch ----------------
__device__ __nv_bfloat16 g_Whi[KPAD * D_MODEL];           // 512 KB
__device__ __nv_bfloat16 g_Wlo[KPAD * D_MODEL];           // 512 KB
__device__ __nv_bfloat16 g_Xhi[TOKENS * D_MODEL];         // 32 MB
__device__ __nv_bfloat16 g_Xlo[TOKENS * D_MODEL];         // 32 MB
__device__ float         g_zpart[KSEGS * TOKENS * KPAD];  // 8 MB

// ---------------- K0: W -> bf16 hi/lo (padded to 128 rows) ----------------
__global__ void prep_wt_kernel(const float* __restrict__ W) {
    int id = blockIdx.x * 256 + threadIdx.x;      // KPAD*D_MODEL
    int k = id >> 11, d = id & (D_MODEL - 1);
    float v = (k < N_SKEW) ? W[k * D_MODEL + d] : 0.f;
    __nv_bfloat16 hi = __float2bfloat16(v);
    __nv_bfloat16 lo = __float2bfloat16(v - __bfloat162float(hi));
    g_Whi[id] = hi;
    g_Wlo[id] = lo;
}

// ---------------- K1: mean over streams -> X hi/lo (pure streaming) ----------------
__global__ void __launch_bounds__(256)
mean_split_kernel(const float* __restrict__ streams) {
    int idx   = blockIdx.x * 256 + threadIdx.x;   // TOKENS*512 float4 slots
    int token = idx >> 9;
    int slot  = idx & 511;
    const float4* tb = reinterpret_cast<const float4*>(streams)
                     + (size_t)token * (N_STREAMS * D_MODEL / 4) + slot;
    float4 v[N_STREAMS];
    #pragma unroll
    for (int n = 0; n < N_STREAMS; n++) v[n] = tb[n * (D_MODEL / 4)];
    #pragma unroll
    for (int s = N_STREAMS / 2; s > 0; s >>= 1)
        #pragma unroll
        for (int n = 0; n < s; n++) {
            v[n].x += v[n+s].x; v[n].y += v[n+s].y;
            v[n].z += v[n+s].z; v[n].w += v[n+s].w;
        }
    float f[4] = { v[0].x * 0.125f, v[0].y * 0.125f, v[0].z * 0.125f, v[0].w * 0.125f };
    __nv_bfloat16 hi[4], lo[4];
    #pragma unroll
    for (int i = 0; i < 4; i++) {
        hi[i] = __float2bfloat16(f[i]);
        lo[i] = __float2bfloat16(f[i] - __bfloat162float(hi[i]));
    }
    *reinterpret_cast<uint2*>(&g_Xhi[(size_t)idx * 4]) = *reinterpret_cast<uint2*>(hi);
    *reinterpret_cast<uint2*>(&g_Xlo[(size_t)idx * 4]) = *reinterpret_cast<uint2*>(lo);
}

// ---------------- K2: mma.sync GEMM  zpart = X * W^T ----------------
__device__ __forceinline__ void mma16816(float c[4], const uint32_t a[4],
                                         uint32_t b0, uint32_t b1) {
    asm volatile(
        "mma.sync.aligned.m16n8k16.row.col.f32.bf16.bf16.f32 "
        "{%0,%1,%2,%3}, {%4,%5,%6,%7}, {%8,%9}, {%0,%1,%2,%3};"
        : "+f"(c[0]), "+f"(c[1]), "+f"(c[2]), "+f"(c[3])
        : "r"(a[0]), "r"(a[1]), "r"(a[2]), "r"(a[3]), "r"(b0), "r"(b1));
}

// smem: Ah[64][PITCH], Al[64][PITCH], Bh[128][PITCH], Bl[128][PITCH] bf16
#define OFF_AH 0
#define OFF_AL (OFF_AH + TILE_M * PITCH * 2)
#define OFF_BH (OFF_AL + TILE_M * PITCH * 2)
#define OFF_BL (OFF_BH + KPAD * PITCH * 2)
#define GEMM_SMEM (OFF_BL + KPAD * PITCH * 2)

__global__ void __launch_bounds__(256, 2)
gemm_z_kernel() {
    extern __shared__ char smem[];
    const int tid  = threadIdx.x;
    const int wid  = tid >> 5;
    const int lane = tid & 31;
    const int g    = lane >> 2;       // group 0..7
    const int t    = lane & 3;        // thread-in-group
    const int tok0 = blockIdx.x * TILE_M;
    const int kseg = blockIdx.y;

    const int wm = (wid & 1) * 32;    // warp row offset (0/32)
    const int wn = (wid >> 1) * 32;   // warp col offset (0/32/64/96)

    float acc[2][4][4];
    #pragma unroll
    for (int mt = 0; mt < 2; mt++)
        #pragma unroll
        for (int nt = 0; nt < 4; nt++)
            #pragma unroll
            for (int i = 0; i < 4; i++) acc[mt][nt][i] = 0.f;

    #pragma unroll 1
    for (int kc = 0; kc < N_KC; kc++) {
        const int d0 = kseg * KSEG_D + kc * KC;

        // stage A (64 rows) and B (128 rows), 8 uint4 per row, hi+lo
        #pragma unroll 1
        for (int i = tid; i < TILE_M * 8; i += 256) {
            int r = i >> 3, q = i & 7;
            size_t gsrc = (size_t)(tok0 + r) * D_MODEL + d0 + q * 8;
            *reinterpret_cast<uint4*>(smem + OFF_AH + r * (PITCH*2) + q * 16) =
                *reinterpret_cast<const uint4*>(&g_Xhi[gsrc]);
            *reinterpret_cast<uint4*>(smem + OFF_AL + r * (PITCH*2) + q * 16) =
                *reinterpret_cast<const uint4*>(&g_Xlo[gsrc]);
        }
        #pragma unroll 1
        for (int i = tid; i < KPAD * 8; i += 256) {
            int r = i >> 3, q = i & 7;
            size_t gsrc = (size_t)r * D_MODEL + d0 + q * 8;
            *reinterpret_cast<uint4*>(smem + OFF_BH + r * (PITCH*2) + q * 16) =
                *reinterpret_cast<const uint4*>(&g_Whi[gsrc]);
            *reinterpret_cast<uint4*>(smem + OFF_BL + r * (PITCH*2) + q * 16) =
                *reinterpret_cast<const uint4*>(&g_Wlo[gsrc]);
        }
        __syncthreads();

        // 4 k16 steps per chunk
        #pragma unroll
        for (int ks = 0; ks < 4; ks++) {
            const int kb = ks * 16 + 2 * t;          // k element base for this lane

            // A fragments for 2 m-tiles, hi and lo
            uint32_t Ah[2][4], Al[2][4];
            #pragma unroll
            for (int mt = 0; mt < 2; mt++) {
                int r0 = wm + mt * 16 + g;
                const char* pah = smem + OFF_AH;
                const char* pal = smem + OFF_AL;
                Ah[mt][0] = *reinterpret_cast<const uint32_t*>(pah + (r0    ) * (PITCH*2) + kb * 2);
                Ah[mt][1] = *reinterpret_cast<const uint32_t*>(pah + (r0 + 8) * (PITCH*2) + kb * 2);
                Ah[mt][2] = *reinterpret_cast<const uint32_t*>(pah + (r0    ) * (PITCH*2) + (kb + 8) * 2);
                Ah[mt][3] = *reinterpret_cast<const uint32_t*>(pah + (r0 + 8) * (PITCH*2) + (kb + 8) * 2);
                Al[mt][0] = *reinterpret_cast<const uint32_t*>(pal + (r0    ) * (PITCH*2) + kb * 2);
                Al[mt][1] = *reinterpret_cast<const uint32_t*>(pal + (r0 + 8) * (PITCH*2) + kb * 2);
                Al[mt][2] = *reinterpret_cast<const uint32_t*>(pal + (r0    ) * (PITCH*2) + (kb + 8) * 2);
                Al[mt][3] = *reinterpret_cast<const uint32_t*>(pal + (r0 + 8) * (PITCH*2) + (kb + 8) * 2);
            }

            #pragma unroll
            for (int nt = 0; nt < 4; nt++) {
                int n0 = wn + nt * 8 + g;
                uint32_t bh0 = *reinterpret_cast<const uint32_t*>(
                    smem + OFF_BH + n0 * (PITCH*2) + kb * 2);
                uint32_t bh1 = *reinterpret_cast<const uint32_t*>(
                    smem + OFF_BH + n0 * (PITCH*2) + (kb + 8) * 2);
                uint32_t bl0 = *reinterpret_cast<const uint32_t*>(
                    smem + OFF_BL + n0 * (PITCH*2) + kb * 2);
                uint32_t bl1 = *reinterpret_cast<const uint32_t*>(
                    smem + OFF_BL + n0 * (PITCH*2) + (kb + 8) * 2);
                #pragma unroll
                for (int mt = 0; mt < 2; mt++) {
                    mma16816(acc[mt][nt], Ah[mt], bh0, bh1);   // hi*hi
                    mma16816(acc[mt][nt], Ah[mt], bl0, bl1);   // hi*lo
                    mma16816(acc[mt][nt], Al[mt], bh0, bh1);   // lo*hi
                }
            }
        }
        __syncthreads();
    }

    // epilogue: write z partial. c0,c1 = D[g][2t..2t+1]; c2,c3 = D[g+8][...]
    float* zp = g_zpart + (size_t)kseg * TOKENS * KPAD;
    #pragma unroll
    for (int mt = 0; mt < 2; mt++)
        #pragma unroll
        for (int nt = 0; nt < 4; nt++) {
            int row = tok0 + wm + mt * 16 + g;
            int col = wn + nt * 8 + 2 * t;
            *reinterpret_cast<float2*>(&zp[(size_t)row * KPAD + col]) =
                make_float2(acc[mt][nt][0], acc[mt][nt][1]);
            *reinterpret_cast<float2*>(&zp[(size_t)(row + 8) * KPAD + col]) =
                make_float2(acc[mt][nt][2], acc[mt][nt][3]);
        }
}

// ---------------- K3: reduce partials + Cayley solve ----------------
#define S_TPC 16
__global__ void __launch_bounds__(512)
solve_kernel(const float* __restrict__ bias, float* __restrict__ out) {
    __shared__ float zs[S_TPC * KPAD];
    const int tid  = threadIdx.x;
    const int tile = blockIdx.x;

    for (int i = tid; i < S_TPC * KPAD; i += 512) {
        int t = i >> 7, k = i & 127;
        size_t base = (size_t)(tile * S_TPC + t) * KPAD + k;
        float z = g_zpart[base] + g_zpart[(size_t)TOKENS * KPAD + base];
        zs[i] = z + ((k < N_SKEW) ? bias[k] : 0.f);
    }
    __syncthreads();

    const int warp = tid >> 5;
    const int lane = tid & 31;
    const int r    = lane & 15;
    const float* zt = zs + warp * KPAD;
    const unsigned mask = 0xffffffffu;

    float m[32];
    #pragma unroll
    for (int cc = 0; cc < NS; cc++) {
        float a = 0.f;
        if (cc > r)      a =  zt[(r * (31 - r)) / 2 + (cc - r - 1)];
        else if (cc < r) a = -zt[(cc * (31 - cc)) / 2 + (r - cc - 1)];
        float diag = (cc == r) ? 1.f : 0.f;
        m[cc]      = diag + a;
        m[16 + cc] = diag - a;
    }
    #pragma unroll
    for (int i = 0; i < NS; i++) {
        float pivi = __shfl_sync(mask, m[i], i);
        float rp = 1.0f / pivi;
        float cf = (r == i) ? (1.0f - rp) : m[i] * rp;
        #pragma unroll
        for (int k = 0; k < 32; k++) {
            float pk = __shfl_sync(mask, m[k], i);
            m[k] = fmaf(-cf, pk, m[k]);
        }
    }
    float hq[8];
    #pragma unroll
    for (int q = 0; q < 8; q++) {
        float q0 = m[16 + 2 * q], q1 = m[16 + 2 * q + 1];
        hq[q] = q0 * q0 + q1 * q1;
    }
    #pragma unroll
    for (int q = 0; q < 8; q++)
        hq[q] += __shfl_xor_sync(mask, hq[q], 1);

    if (lane < 16 && !(r & 1)) {
        const int tok = tile * S_TPC + warp;
        float* o = out + (size_t)tok * 64 + (r >> 1) * 8;
        #pragma unroll
        for (int q = 0; q < 8; q++) o[q] = 0.5f * hq[q];
    }
}

// ---------------- launch ----------------
extern "C" void kernel_launch(void* const* d_in, const int* in_sizes, int n_in,
                              void* d_out, int out_size) {
    const float* streams = (const float*)d_in[0];
    const float* W       = (const float*)d_in[1];
    const float* b       = (const float*)d_in[2];
    float* out = (float*)d_out;

    prep_wt_kernel<<<(KPAD * D_MODEL) / 256, 256>>>(W);
    mean_split_kernel<<<TOKENS * (D_MODEL / 4) / 256, 256>>>(streams);

    cudaFuncSetAttribute(gemm_z_kernel,
                         cudaFuncAttributeMaxDynamicSharedMemorySize, GEMM_SMEM);
    gemm_z_kernel<<<dim3(M_TILES, KSEGS), 256, GEMM_SMEM>>>();

    solve_kernel<<<TOKENS / S_TPC, 512>>>(b, out);
}

// round 9
// speedup vs baseline: 2.3654x; 1.4813x over previous
#include <cuda_runtime.h>
#include <cuda_bf16.h>
#include <cstdint>

// ---------------- problem constants ----------------
#define N_STREAMS 8
#define D_MODEL   2048
#define NS        16
#define N_SKEW    120
#define KPAD      128
#define TOKENS    8192

#define TILE_M    64
#define M_TILES   (TOKENS / TILE_M)    // 128
#define KC        64                   // d per chunk
#define NC        (D_MODEL / KC)       // 32 chunks
#define PITCH_B   144                  // row pitch bytes (72 bf16)

// smem layout (bytes):
//   A tiles:  [buf][hi/lo][64 rows][144]   -> 4 * 9216  = 36864
//   B tiles:  [buf][hi/lo][128 rows][144]  -> 4 * 18432 = 73728 (at 36864)
//   z (alias over A region, used after mainloop): 64*128*4 = 32768
//   bias smem at byte 32768 (within A region, after z? no -> place at end)
#define A_OFF(buf, hl) (((buf) * 2 + (hl)) * 9216)
#define B_BASE 36864
#define B_OFF(buf, hl) (B_BASE + ((buf) * 2 + (hl)) * 18432)
#define BIAS_OFF (B_BASE + 73728)            // 128 floats = 512 B
#define SMEM_TOTAL (BIAS_OFF + 512)

// ---------------- device scratch ----------------
__device__ __nv_bfloat16 g_Whi[KPAD * D_MODEL];   // 512 KB
__device__ __nv_bfloat16 g_Wlo[KPAD * D_MODEL];   // 512 KB

// ---------------- K0: W -> bf16 hi/lo (padded to 128 rows) ----------------
__global__ void prep_wt_kernel(const float* __restrict__ W) {
    int id = blockIdx.x * 256 + threadIdx.x;      // KPAD*D_MODEL
    int k = id >> 11, d = id & (D_MODEL - 1);
    float v = (k < N_SKEW) ? W[k * D_MODEL + d] : 0.f;
    __nv_bfloat16 hi = __float2bfloat16(v);
    __nv_bfloat16 lo = __float2bfloat16(v - __bfloat162float(hi));
    g_Whi[id] = hi;
    g_Wlo[id] = lo;
}

// ---------------- fused kernel ----------------
__device__ __forceinline__ void mma16816(float c[4], const uint32_t a[4],
                                         uint32_t b0, uint32_t b1) {
    asm volatile(
        "mma.sync.aligned.m16n8k16.row.col.f32.bf16.bf16.f32 "
        "{%0,%1,%2,%3}, {%4,%5,%6,%7}, {%8,%9}, {%0,%1,%2,%3};"
        : "+f"(c[0]), "+f"(c[1]), "+f"(c[2]), "+f"(c[3])
        : "r"(a[0]), "r"(a[1]), "r"(a[2]), "r"(a[3]), "r"(b0), "r"(b1));
}

__global__ void __launch_bounds__(512, 1)
gomhc_fused_kernel(const float* __restrict__ streams,
                   const float* __restrict__ bias,
                   float* __restrict__ out) {
    extern __shared__ char smem[];
    const int tid  = threadIdx.x;
    const int wid  = tid >> 5;
    const int lane = tid & 31;
    const int tile = blockIdx.x;
    const int tok0 = tile * TILE_M;

    // stage bias into smem (used only in solve tail)
    if (tid < KPAD)
        *reinterpret_cast<float*>(smem + BIAS_OFF + tid * 4) =
            (tid < N_SKEW) ? bias[tid] : 0.f;

    const bool producer = (wid >= 8);

    // =================== producer prologue: chunk 0 ===================
    if (producer) {
        const int ptid = tid - 256;              // 0..255
        // A: 4 (token, slot) pairs; 64 tok x 16 slots (slot = 4 floats)
        #pragma unroll
        for (int p = 0; p < 4; p++) {
            int idx  = ptid + p * 256;
            int tk   = idx >> 4;
            int slot = idx & 15;
            const float4* src = reinterpret_cast<const float4*>(streams)
                + ((size_t)(tok0 + tk) * N_STREAMS * D_MODEL + slot * 4) / 4;
            float4 v[N_STREAMS];
            #pragma unroll
            for (int n = 0; n < N_STREAMS; n++) v[n] = src[n * (D_MODEL / 4)];
            #pragma unroll
            for (int s = N_STREAMS / 2; s > 0; s >>= 1)
                #pragma unroll
                for (int n = 0; n < s; n++) {
                    v[n].x += v[n+s].x; v[n].y += v[n+s].y;
                    v[n].z += v[n+s].z; v[n].w += v[n+s].w;
                }
            float f[4] = { v[0].x*0.125f, v[0].y*0.125f, v[0].z*0.125f, v[0].w*0.125f };
            __nv_bfloat16 hi[4], lo[4];
            #pragma unroll
            for (int i = 0; i < 4; i++) {
                hi[i] = __float2bfloat16(f[i]);
                lo[i] = __float2bfloat16(f[i] - __bfloat162float(hi[i]));
            }
            *reinterpret_cast<uint2*>(smem + A_OFF(0,0) + tk * PITCH_B + slot * 8) =
                *reinterpret_cast<uint2*>(hi);
            *reinterpret_cast<uint2*>(smem + A_OFF(0,1) + tk * PITCH_B + slot * 8) =
                *reinterpret_cast<uint2*>(lo);
        }
        // B: 128 rows x 8 quads (16B each)
        #pragma unroll
        for (int p = 0; p < 4; p++) {
            int idx = ptid + p * 256;
            int r = idx >> 3, q = idx & 7;
            size_t gsrc = (size_t)r * D_MODEL + q * 8;
            *reinterpret_cast<uint4*>(smem + B_OFF(0,0) + r * PITCH_B + q * 16) =
                *reinterpret_cast<const uint4*>(&g_Whi[gsrc]);
            *reinterpret_cast<uint4*>(smem + B_OFF(0,1) + r * PITCH_B + q * 16) =
                *reinterpret_cast<const uint4*>(&g_Wlo[gsrc]);
        }
    }

    // consumer accumulators
    const int g  = lane >> 2;
    const int t  = lane & 3;
    const int wm = (wid & 1) * 32;
    const int wn = (wid >> 1) * 32;
    float acc[2][4][4];
    #pragma unroll
    for (int mt = 0; mt < 2; mt++)
        #pragma unroll
        for (int nt = 0; nt < 4; nt++)
            #pragma unroll
            for (int i = 0; i < 4; i++) acc[mt][nt][i] = 0.f;

    __syncthreads();   // buffer 0 ready

    // =================== main loop ===================
    #pragma unroll 1
    for (int c = 0; c < NC; c++) {
        const int buf = c & 1;

        if (producer) {
            if (c + 1 < NC) {
                const int ptid = tid - 256;
                const int d0 = (c + 1) * KC;
                const int nb = (c + 1) & 1;
                #pragma unroll
                for (int p = 0; p < 4; p++) {
                    int idx  = ptid + p * 256;
                    int tk   = idx >> 4;
                    int slot = idx & 15;
                    const float4* src = reinterpret_cast<const float4*>(streams)
                        + ((size_t)(tok0 + tk) * N_STREAMS * D_MODEL + d0 + slot * 4) / 4;
                    float4 v[N_STREAMS];
                    #pragma unroll
                    for (int n = 0; n < N_STREAMS; n++) v[n] = src[n * (D_MODEL / 4)];
                    #pragma unroll
                    for (int s = N_STREAMS / 2; s > 0; s >>= 1)
                        #pragma unroll
                        for (int n = 0; n < s; n++) {
                            v[n].x += v[n+s].x; v[n].y += v[n+s].y;
                            v[n].z += v[n+s].z; v[n].w += v[n+s].w;
                        }
                    float f[4] = { v[0].x*0.125f, v[0].y*0.125f, v[0].z*0.125f, v[0].w*0.125f };
                    __nv_bfloat16 hi[4], lo[4];
                    #pragma unroll
                    for (int i = 0; i < 4; i++) {
                        hi[i] = __float2bfloat16(f[i]);
                        lo[i] = __float2bfloat16(f[i] - __bfloat162float(hi[i]));
                    }
                    *reinterpret_cast<uint2*>(smem + A_OFF(nb,0) + tk * PITCH_B + slot * 8) =
                        *reinterpret_cast<uint2*>(hi);
                    *reinterpret_cast<uint2*>(smem + A_OFF(nb,1) + tk * PITCH_B + slot * 8) =
                        *reinterpret_cast<uint2*>(lo);
                }
                #pragma unroll
                for (int p = 0; p < 4; p++) {
                    int idx = (tid - 256) + p * 256;
                    int r = idx >> 3, q = idx & 7;
                    size_t gsrc = (size_t)r * D_MODEL + d0 + q * 8;
                    *reinterpret_cast<uint4*>(smem + B_OFF(nb,0) + r * PITCH_B + q * 16) =
                        *reinterpret_cast<const uint4*>(&g_Whi[gsrc]);
                    *reinterpret_cast<uint4*>(smem + B_OFF(nb,1) + r * PITCH_B + q * 16) =
                        *reinterpret_cast<const uint4*>(&g_Wlo[gsrc]);
                }
            }
        } else {
            // consumer: 4 k16 steps on this chunk
            const char* pah = smem + A_OFF(buf, 0);
            const char* pal = smem + A_OFF(buf, 1);
            const char* pbh = smem + B_OFF(buf, 0);
            const char* pbl = smem + B_OFF(buf, 1);
            #pragma unroll
            for (int ks = 0; ks < 4; ks++) {
                const int kb = ks * 16 + 2 * t;
                uint32_t Ah[2][4], Al[2][4];
                #pragma unroll
                for (int mt = 0; mt < 2; mt++) {
                    int r0 = wm + mt * 16 + g;
                    Ah[mt][0] = *reinterpret_cast<const uint32_t*>(pah + (r0    ) * PITCH_B + kb * 2);
                    Ah[mt][1] = *reinterpret_cast<const uint32_t*>(pah + (r0 + 8) * PITCH_B + kb * 2);
                    Ah[mt][2] = *reinterpret_cast<const uint32_t*>(pah + (r0    ) * PITCH_B + (kb + 8) * 2);
                    Ah[mt][3] = *reinterpret_cast<const uint32_t*>(pah + (r0 + 8) * PITCH_B + (kb + 8) * 2);
                    Al[mt][0] = *reinterpret_cast<const uint32_t*>(pal + (r0    ) * PITCH_B + kb * 2);
                    Al[mt][1] = *reinterpret_cast<const uint32_t*>(pal + (r0 + 8) * PITCH_B + kb * 2);
                    Al[mt][2] = *reinterpret_cast<const uint32_t*>(pal + (r0    ) * PITCH_B + (kb + 8) * 2);
                    Al[mt][3] = *reinterpret_cast<const uint32_t*>(pal + (r0 + 8) * PITCH_B + (kb + 8) * 2);
                }
                #pragma unroll
                for (int nt = 0; nt < 4; nt++) {
                    int n0 = wn + nt * 8 + g;
                    uint32_t bh0 = *reinterpret_cast<const uint32_t*>(pbh + n0 * PITCH_B + kb * 2);
                    uint32_t bh1 = *reinterpret_cast<const uint32_t*>(pbh + n0 * PITCH_B + (kb + 8) * 2);
                    uint32_t bl0 = *reinterpret_cast<const uint32_t*>(pbl + n0 * PITCH_B + kb * 2);
                    uint32_t bl1 = *reinterpret_cast<const uint32_t*>(pbl + n0 * PITCH_B + (kb + 8) * 2);
                    #pragma unroll
                    for (int mt = 0; mt < 2; mt++) {
                        mma16816(acc[mt][nt], Ah[mt], bh0, bh1);
                        mma16816(acc[mt][nt], Ah[mt], bl0, bl1);
                        mma16816(acc[mt][nt], Al[mt], bh0, bh1);
                    }
                }
            }
        }
        __syncthreads();
    }

    // =================== epilogue: z -> smem (alias over A region) ===================
    float* zs = reinterpret_cast<float*>(smem);    // [64][128] = 32 KB
    if (!producer) {
        #pragma unroll
        for (int mt = 0; mt < 2; mt++)
            #pragma unroll
            for (int nt = 0; nt < 4; nt++) {
                int row = wm + mt * 16 + g;
                int col = wn + nt * 8 + 2 * t;
                *reinterpret_cast<float2*>(&zs[row * KPAD + col]) =
                    make_float2(acc[mt][nt][0], acc[mt][nt][1]);
                *reinterpret_cast<float2*>(&zs[(row + 8) * KPAD + col]) =
                    make_float2(acc[mt][nt][2], acc[mt][nt][3]);
            }
    }
    __syncthreads();

    // =================== solve: 16 warps x 2 passes x 2 tokens ===================
    {
        const float* bs = reinterpret_cast<const float*>(smem + BIAS_OFF);
        const int half = lane >> 4;                 // 0/1
        const int r    = lane & 15;
        const unsigned mask = 0xffffffffu;

        #pragma unroll 1
        for (int pass = 0; pass < 2; pass++) {
            const int tk = wid * 4 + pass * 2 + half;   // 0..63
            const float* zt = zs + tk * KPAD;

            float m[32];
            #pragma unroll
            for (int cc = 0; cc < NS; cc++) {
                float a = 0.f;
                if (cc > r) {
                    int u = (r * (31 - r)) / 2 + (cc - r - 1);
                    a = zt[u] + bs[u];
                } else if (cc < r) {
                    int u = (cc * (31 - cc)) / 2 + (r - cc - 1);
                    a = -(zt[u] + bs[u]);
                }
                float diag = (cc == r) ? 1.f : 0.f;
                m[cc]      = diag + a;
                m[16 + cc] = diag - a;
            }

            #pragma unroll
            for (int i = 0; i < NS; i++) {
                const int src = i + (half << 4);
                float pivi = __shfl_sync(mask, m[i], src);
                float rp = 1.0f / pivi;
                float cf = (r == i) ? (1.0f - rp) : m[i] * rp;
                #pragma unroll
                for (int k = 0; k < 32; k++) {
                    float pk = __shfl_sync(mask, m[k], src);
                    m[k] = fmaf(-cf, pk, m[k]);
                }
            }

            float hq[8];
            #pragma unroll
            for (int q = 0; q < 8; q++) {
                float q0 = m[16 + 2 * q], q1 = m[16 + 2 * q + 1];
                hq[q] = q0 * q0 + q1 * q1;
            }
            #pragma unroll
            for (int q = 0; q < 8; q++)
                hq[q] += __shfl_xor_sync(mask, hq[q], 1);

            if (!(r & 1)) {
                const int tok = tok0 + tk;
                float* o = out + (size_t)tok * 64 + (r >> 1) * 8;
                #pragma unroll
                for (int q = 0; q < 8; q++) o[q] = 0.5f * hq[q];
            }
        }
    }
}

// ---------------- launch ----------------
extern "C" void kernel_launch(void* const* d_in, const int* in_sizes, int n_in,
                              void* d_out, int out_size) {
    const float* streams = (const float*)d_in[0];
    const float* W       = (const float*)d_in[1];
    const float* b       = (const float*)d_in[2];
    float* out = (float*)d_out;

    prep_wt_kernel<<<(KPAD * D_MODEL) / 256, 256>>>(W);

    cudaFuncSetAttribute(gomhc_fused_kernel,
                         cudaFuncAttributeMaxDynamicSharedMemorySize, SMEM_TOTAL);
    gomhc_fused_kernel<<<M_TILES, 512, SMEM_TOTAL>>>(streams, b, out);
}